// round 9
// baseline (speedup 1.0000x reference)
#include <cuda_runtime.h>
#include <math.h>

#define Bc 8
#define Sc 512
#define Nc (Sc*Sc)
#define NBs 128
#define TPBs 256
#define CPBs (Nc/NBs)
#define ITERS 20
#define EPSF 1e-6f
#define INVH 511.0f
#define HF (1.0f/511.0f)
#define HH (HF*HF)
#define GAMMA_F 10.0f
#define THRESH_F 0.5f

// persistent kernel config
#define PB 256
#define PT 512
#define BPB 32
#define ROWS 16

// ---- scratch ----
__device__ float g_cxs[Bc*(Sc-1)*Sc];
__device__ float g_cys[Bc*Sc*(Sc-1)];
__device__ float g_lap[Bc*Nc];
__device__ float g_rho[Bc*Nc];
__device__ float g_P[Bc*Nc];
__device__ float g_Q[Bc*Nc];
__device__ float g_BB[Bc*Nc];
__device__ float g_BNX[Bc*Nc];
__device__ float g_BNY[Bc*Nc];
__device__ float g_RB[Nc];
__device__ float g_r[Bc*Nc];            // rhs from s2
__device__ float g_w[Bc*Nc];            // only edge rows used during CG
__device__ float2 g_part[Bc*BPB];
__device__ unsigned g_cnt[Bc];
__device__ unsigned long long g_pubA[Bc];
__device__ unsigned long long g_pubB[Bc];

// =====================================================================
// S1
// =====================================================================
__global__ void s1_kernel(const float* __restrict__ coeff,
                          const float* __restrict__ u,
                          const float* __restrict__ beta) {
    int b = blockIdx.y;
    size_t off = (size_t)b * Nc;
    const float* C = coeff + off;
    const float* U = u + off;
    const float4* B4 = (const float4*)beta + off;
    int base = blockIdx.x * CPBs;

    for (int t = threadIdx.x; t < CPBs; t += TPBs) {
        int idx = base + t;
        int i = idx >> 9;
        int j = idx & (Sc - 1);
        float c = C[idx];

        if (i < Sc - 1) {
            float cn = C[idx + Sc];
            g_cxs[(size_t)b*(Sc-1)*Sc + idx] = (2.f*c*cn / (c + cn + EPSF)) * (INVH*INVH);
        }
        if (j < Sc - 1) {
            float ce = C[idx + 1];
            g_cys[(size_t)b*Sc*(Sc-1) + (size_t)i*(Sc-1) + j] = (2.f*c*ce / (c + ce + EPSF)) * (INVH*INVH);
        }

        float lap = 0.f;
        if (i > 0 && i < Sc-1 && j > 0 && j < Sc-1) {
            float uc = U[idx];
            lap = ((U[idx+Sc]-uc)*INVH - (uc-U[idx-Sc])*INVH)*INVH
                + ((U[idx+1 ]-uc)*INVH - (uc-U[idx-1 ])*INVH)*INVH;
        }
        g_lap[off + idx] = lap;

        float lc = logf(fmaxf(c, EPSF));
        float glx, gly;
        if (i == 0)          glx = (logf(fmaxf(C[idx+Sc],EPSF)) - lc) * INVH;
        else if (i == Sc-1)  glx = (lc - logf(fmaxf(C[idx-Sc],EPSF))) * INVH;
        else                 glx = (logf(fmaxf(C[idx+Sc],EPSF)) - logf(fmaxf(C[idx-Sc],EPSF))) * (0.5f*INVH);
        if (j == 0)          gly = (logf(fmaxf(C[idx+1],EPSF)) - lc) * INVH;
        else if (j == Sc-1)  gly = (lc - logf(fmaxf(C[idx-1],EPSF))) * INVH;
        else                 gly = (logf(fmaxf(C[idx+1],EPSF)) - logf(fmaxf(C[idx-1],EPSF))) * (0.5f*INVH);

        float eta = sqrtf(glx*glx + gly*gly + EPSF);
        float rho = 1.f / (1.f + expf(-GAMMA_F * (eta - THRESH_F)));
        float nhx = glx / eta, nhy = gly / eta;

        float4 bv = B4[idx];
        g_rho[off+idx] = rho;
        g_P[off+idx]   = bv.y*nhx - bv.z*nhy;
        g_Q[off+idx]   = bv.y*nhy + bv.z*nhx;
        g_BB[off+idx]  = bv.x;

        double dl = 1.0 / 511.0;
        double xx = (i == Sc-1) ? 1.0 : (double)i * dl;
        double yy = (j == Sc-1) ? 1.0 : (double)j * dl;
        double a0 = xx, a1 = 1.0 - xx, a2 = yy, a3 = 1.0 - yy;
        double best = a0; int k = 0;
        if (a1 < best) { best = a1; k = 1; }
        if (a2 < best) { best = a2; k = 2; }
        if (a3 < best) { best = a3; k = 3; }
        float bnx = (k == 0) ? -1.f : ((k == 1) ? 1.f : 0.f);
        float bny = (k == 2) ? -1.f : ((k == 3) ? 1.f : 0.f);
        g_BNX[off+idx] = bv.w * bnx;
        g_BNY[off+idx] = bv.w * bny;
        if (b == 0) {
            float dd = (float)best;
            g_RB[idx] = expf(-(dd*dd) / (0.15f*0.15f));
        }
    }
}

// =====================================================================
// S2: rhs -> g_r
// =====================================================================
__device__ __forceinline__ float fluxX(const float* C, const float* U, const float* LAP,
                                       const float* RHO, const float* PP, const float* BB,
                                       const float* BNX, int a) {
    int b2 = a + Sc;
    float ca = C[a], cb = C[b2];
    float cxf = 2.f*ca*cb / (ca + cb + EPSF);
    float gux = (U[b2] - U[a]) * INVH;
    float lgx = (LAP[b2] - LAP[a]) * INVH;
    return 0.5f*(BB[a]+BB[b2]) * HH * cxf * lgx
         + 0.5f*(RHO[a]+RHO[b2]) * (0.5f*(PP[a]+PP[b2])) * cxf * gux
         + 0.5f*(g_RB[a]+g_RB[b2]) * (0.5f*(BNX[a]+BNX[b2])) * cxf * gux;
}

__device__ __forceinline__ float fluxY(const float* C, const float* U, const float* LAP,
                                       const float* RHO, const float* QQ, const float* BB,
                                       const float* BNY, int a) {
    int b2 = a + 1;
    float ca = C[a], cb = C[b2];
    float cyf = 2.f*ca*cb / (ca + cb + EPSF);
    float guy = (U[b2] - U[a]) * INVH;
    float lgy = (LAP[b2] - LAP[a]) * INVH;
    return 0.5f*(BB[a]+BB[b2]) * HH * cyf * lgy
         + 0.5f*(RHO[a]+RHO[b2]) * (0.5f*(QQ[a]+QQ[b2])) * cyf * guy
         + 0.5f*(g_RB[a]+g_RB[b2]) * (0.5f*(BNY[a]+BNY[b2])) * cyf * guy;
}

__global__ void s2_kernel(const float* __restrict__ coeff, const float* __restrict__ u) {
    int b = blockIdx.y;
    size_t off = (size_t)b * Nc;
    const float* C = coeff + off;
    const float* U = u + off;
    const float* LAP = g_lap + off;
    const float* RHO = g_rho + off;
    const float* PP  = g_P + off;
    const float* QQ  = g_Q + off;
    const float* BB  = g_BB + off;
    const float* BNX = g_BNX + off;
    const float* BNY = g_BNY + off;
    int base = blockIdx.x * CPBs;

    for (int t = threadIdx.x; t < CPBs; t += TPBs) {
        int idx = base + t;
        int i = idx >> 9;
        int j = idx & (Sc - 1);
        float rhs = 0.f;
        if (i > 0 && i < Sc-1 && j > 0 && j < Sc-1) {
            float fxN = fluxX(C, U, LAP, RHO, PP, BB, BNX, idx);
            float fxS = fluxX(C, U, LAP, RHO, PP, BB, BNX, idx - Sc);
            float fyE = fluxY(C, U, LAP, RHO, QQ, BB, BNY, idx);
            float fyW = fluxY(C, U, LAP, RHO, QQ, BB, BNY, idx - 1);
            rhs = (fxN - fxS) * INVH + (fyE - fyW) * INVH;
        }
        g_r[off+idx] = rhs;
    }
}

__global__ void zc_kernel() {
    if (threadIdx.x < Bc) {
        g_cnt[threadIdx.x] = 0u;
        g_pubA[threadIdx.x] = 0ull;
        g_pubB[threadIdx.x] = 0ull;
    }
}

// =====================================================================
// one barrier: deterministic reduction of TWO dot products + fence
// =====================================================================
__device__ __forceinline__ float2 sync_reduce2(float va, float vb, float* sRed,
                                               int b, int rblk, unsigned ev) {
#pragma unroll
    for (int o = 16; o > 0; o >>= 1) {
        va += __shfl_down_sync(0xffffffffu, va, o);
        vb += __shfl_down_sync(0xffffffffu, vb, o);
    }
    if ((threadIdx.x & 31) == 0) {
        sRed[2*(threadIdx.x >> 5)]   = va;
        sRed[2*(threadIdx.x >> 5)+1] = vb;
    }
    __syncthreads();
    if (threadIdx.x == 0) {
        float sa = 0.f, sb = 0.f;
#pragma unroll
        for (int w = 0; w < 16; w++) { sa += sRed[2*w]; sb += sRed[2*w+1]; }
        g_part[b*BPB + rblk] = make_float2(sa, sb);
        unsigned old;
        asm volatile("atom.acq_rel.gpu.global.add.u32 %0, [%1], %2;"
                     : "=r"(old) : "l"(&g_cnt[b]), "r"(1u) : "memory");
        if (old == ev*BPB - 1u) {
            const float2* pp = &g_part[b*BPB];
            float ga = 0.f, gb2 = 0.f;
#pragma unroll
            for (int i = 0; i < BPB; i++) { float2 v = pp[i]; ga += v.x; gb2 += v.y; }
            unsigned long long pkA = ((unsigned long long)ev << 32) |
                                     (unsigned long long)__float_as_uint(ga);
            unsigned long long pkB = ((unsigned long long)ev << 32) |
                                     (unsigned long long)__float_as_uint(gb2);
            asm volatile("st.release.gpu.global.b64 [%0], %1;" :: "l"(&g_pubA[b]), "l"(pkA) : "memory");
            asm volatile("st.release.gpu.global.b64 [%0], %1;" :: "l"(&g_pubB[b]), "l"(pkB) : "memory");
            sRed[0] = ga; sRed[1] = gb2;
        } else {
            unsigned long long pk;
            do {
                asm volatile("ld.acquire.gpu.global.b64 %0, [%1];"
                             : "=l"(pk) : "l"(&g_pubB[b]) : "memory");
            } while ((unsigned)(pk >> 32) != ev);
            sRed[1] = __uint_as_float((unsigned)pk);
            do {
                asm volatile("ld.acquire.gpu.global.b64 %0, [%1];"
                             : "=l"(pk) : "l"(&g_pubA[b]) : "memory");
            } while ((unsigned)(pk >> 32) != ev);
            sRed[0] = __uint_as_float((unsigned)pk);
        }
    }
    __syncthreads();
    float2 r = make_float2(sRed[0], sRed[1]);
    __syncthreads();
    return r;
}

#define SMEM_FLOATS (3*16*PT + 64)
#define SMEM_BYTES (SMEM_FLOATS * 4)

// =====================================================================
// Persistent pipelined-CG kernel (Ghysels-Vanroose): 1 barrier/iteration
// =====================================================================
__global__ void __launch_bounds__(PT, 2)
cg_kernel(const float* __restrict__ u, float* __restrict__ out) {
    extern __shared__ float sm[];
    float* sW   = sm;                 // w  (stencil field: cross-thread access)
    float* sS   = sm + 16*PT;         // s = A p
    float* sZ   = sS + 16*PT;         // z = A s
    float* sRed = sZ + 16*PT;         // 64 floats scratch

    const int t = threadIdx.x;
    const int blk = blockIdx.x;
    const int b = blk >> 5;
    const int rblk = blk & 31;
    const int R0 = rblk * ROWS;
    const size_t off = (size_t)b * Nc;
    const size_t gb = off + (size_t)R0 * Sc + t;
    const float* __restrict__ CX = g_cxs + (size_t)b*(Sc-1)*Sc;
    const float* __restrict__ CY = g_cys + (size_t)b*Sc*(Sc-1);
    unsigned ev = 0;

    const bool interiorT = (t > 0 && t < Sc-1);
    float r[ROWS], p[ROWS], x[ROWS];

    // ---- init: r from g_r; stage r in sS; w0 = A r0; partials (r.r, w.r) ----
#pragma unroll
    for (int k = 0; k < ROWS; k++) {
        float rv = g_r[gb + k*Sc];
        r[k] = rv;
        sS[k*PT + t] = rv;            // staging for stencil
        x[k] = 0.f;
        p[k] = 0.f;
    }
    __syncthreads();

    float accA = 0.f, accB = 0.f;
    {
        float rHT = (rblk > 0)     ? g_r[gb - Sc]      : 0.f;
        float rHB = (rblk < BPB-1) ? g_r[gb + ROWS*Sc] : 0.f;
        float cxp = CX[(size_t)(R0 > 0 ? R0-1 : 0)*Sc + t];
#pragma unroll
        for (int k = 0; k < ROWS; k++) {
            int i = R0 + k;
            int icx = (i < Sc-1) ? i : Sc-2;
            float cxn = CX[(size_t)icx*Sc + t];
            float w = 0.f;
            if (i > 0 && i < Sc-1 && interiorT) {
                float rc = r[k];
                float ru = (k == ROWS-1) ? rHB : sS[(k+1)*PT + t];
                float rd = (k == 0)      ? rHT : sS[(k-1)*PT + t];
                float re = sS[k*PT + t + 1];
                float rw_ = sS[k*PT + t - 1];
                float cye = CY[(size_t)i*(Sc-1) + t];
                float cyw = CY[(size_t)i*(Sc-1) + t - 1];
                w = cxn*(rc-ru) + cxp*(rc-rd) + cye*(rc-re) + cyw*(rc-rw_);
            }
            sW[k*PT + t] = w;
            accA += r[k]*r[k];
            accB += w*r[k];
            if (k == 0 || k == ROWS-1) g_w[gb + k*Sc] = w;
            cxp = cxn;
        }
    }
    __syncthreads();   // all sS (r-staging) reads done
#pragma unroll
    for (int k = 0; k < ROWS; k++) { sS[k*PT + t] = 0.f; sZ[k*PT + t] = 0.f; }
    // (no cross-thread reads of sS/sZ until after next barrier's syncthreads)

    float gamma_old = 1.f, alpha_old = 1.f;

    for (int it = 0; it < ITERS; it++) {
        ev++;
        float2 gd = sync_reduce2(accA, accB, sRed, b, rblk, ev);
        float G = gd.x, D = gd.y;
        float beta, alpha;
        if (it == 0) {
            beta = 0.f;
            alpha = G / fmaxf(D, EPSF);
        } else {
            beta = G / fmaxf(gamma_old, EPSF);
            float den = D - beta * G / alpha_old;
            alpha = G / fmaxf(den, EPSF);
        }

        if (it == ITERS-1) {
            // final: only x needs updating
#pragma unroll
            for (int k = 0; k < ROWS; k++) {
                float pv = r[k] + beta * p[k];
                x[k] += alpha * pv;
            }
            break;
        }

        // ---- pass 1: q = A w ; z = q + beta*z ----
        {
            float wHT = (rblk > 0)     ? g_w[gb - Sc]      : 0.f;
            float wHB = (rblk < BPB-1) ? g_w[gb + ROWS*Sc] : 0.f;
            float cxp = CX[(size_t)(R0 > 0 ? R0-1 : 0)*Sc + t];
#pragma unroll
            for (int k = 0; k < ROWS; k++) {
                int i = R0 + k;
                int icx = (i < Sc-1) ? i : Sc-2;
                float cxn = CX[(size_t)icx*Sc + t];
                float q = 0.f;
                if (i > 0 && i < Sc-1 && interiorT) {
                    float wc = sW[k*PT + t];
                    float wu = (k == ROWS-1) ? wHB : sW[(k+1)*PT + t];
                    float wd = (k == 0)      ? wHT : sW[(k-1)*PT + t];
                    float we = sW[k*PT + t + 1];
                    float ww = sW[k*PT + t - 1];
                    float cye = CY[(size_t)i*(Sc-1) + t];
                    float cyw = CY[(size_t)i*(Sc-1) + t - 1];
                    q = cxn*(wc-wu) + cxp*(wc-wd) + cye*(wc-we) + cyw*(wc-ww);
                }
                sZ[k*PT + t] = q + beta * sZ[k*PT + t];
                cxp = cxn;
            }
        }
        __syncthreads();  // all sW stencil reads done before pass 2 overwrites sW

        // ---- pass 2: recurrences + next partials + edge-w exchange ----
        accA = 0.f; accB = 0.f;
#pragma unroll
        for (int k = 0; k < ROWS; k++) {
            float wc = sW[k*PT + t];
            float sv = wc + beta * sS[k*PT + t];
            sS[k*PT + t] = sv;
            float pv = r[k] + beta * p[k];
            p[k] = pv;
            x[k] += alpha * pv;
            float rv = r[k] - alpha * sv;
            r[k] = rv;
            float wv = wc - alpha * sZ[k*PT + t];
            sW[k*PT + t] = wv;
            accA += rv * rv;
            accB += wv * rv;
            if (k == 0 || k == ROWS-1) g_w[gb + k*Sc] = wv;
        }
        gamma_old = G;
        alpha_old = alpha;
        // next sync_reduce2's __syncthreads orders pass-2 sW writes vs next pass-1 reads
    }

    // ---- output: out = zb(u + x) ----
#pragma unroll
    for (int k = 0; k < ROWS; k++) {
        int i = R0 + k;
        size_t gi = gb + k*Sc;
        float v = 0.f;
        if (i > 0 && i < Sc-1 && interiorT) v = u[gi] + x[k];
        out[gi] = v;
    }
}

extern "C" void kernel_launch(void* const* d_in, const int* in_sizes, int n_in,
                              void* d_out, int out_size) {
    const float* coeff = (const float*)d_in[0];
    const float* u     = (const float*)d_in[1];
    const float* beta  = (const float*)d_in[2];
    float* out = (float*)d_out;

    cudaFuncSetAttribute(cg_kernel, cudaFuncAttributeMaxDynamicSharedMemorySize, SMEM_BYTES);

    zc_kernel<<<1, 32>>>();
    dim3 grid(NBs, Bc), blkd(TPBs);
    s1_kernel<<<grid, blkd>>>(coeff, u, beta);
    s2_kernel<<<grid, blkd>>>(coeff, u);
    cg_kernel<<<PB, PT, SMEM_BYTES>>>(u, out);
}

// round 12
// speedup vs baseline: 1.1214x; 1.1214x over previous
#include <cuda_runtime.h>
#include <math.h>

#define Bc 8
#define Sc 512
#define Nc (Sc*Sc)
#define ITERS 20
#define EPSF 1e-6f
#define INVH 511.0f
#define HF (1.0f/511.0f)
#define HH (HF*HF)
#define INVH2 (511.0f*511.0f)
#define GAMMA_F 10.0f
#define THRESH_F 0.5f

// persistent kernel config: 296 = 2*148 blocks, perfectly balanced
#define PT 512
#define BPB 37
#define PB (Bc*BPB)        // 296
#define RMAX 14

// ---- scratch ----
__device__ float2 g_cf[Bc*Nc];          // packed (cx_north, cy_east) * 1/h^2
__device__ float g_lap[Bc*Nc];
__device__ float g_rho[Bc*Nc];
__device__ float g_P[Bc*Nc];
__device__ float g_Q[Bc*Nc];
__device__ float g_BB[Bc*Nc];
__device__ float g_BNX[Bc*Nc];
__device__ float g_BNY[Bc*Nc];
__device__ float g_RB[Nc];
__device__ float g_r[Bc*Nc];
__device__ float g_w[Bc*Nc];            // edge rows only during CG
__device__ float2 g_part[Bc*BPB];
__device__ unsigned g_cnt[Bc];
__device__ unsigned long long g_pubA[Bc];
__device__ unsigned long long g_pubB[Bc];

// =====================================================================
// S1: per-cell precompute. Block = 4 rows x 512 cols, smem log tiles.
// =====================================================================
__global__ void __launch_bounds__(512)
s1_kernel(const float* __restrict__ coeff,
          const float* __restrict__ u,
          const float* __restrict__ beta) {
    __shared__ float sC[6][Sc];
    __shared__ float sL[6][Sc];
    __shared__ float sU[6][Sc];
    int b = blockIdx.y;
    int r0 = blockIdx.x * 4;
    int t = threadIdx.x;
    size_t off = (size_t)b * Nc;
    const float4* B4 = (const float4*)beta + off;

    for (int rr = 0; rr < 6; rr++) {
        int i = r0 - 1 + rr;
        bool in = (i >= 0 && i < Sc);
        float c = in ? coeff[off + (size_t)i*Sc + t] : 0.f;
        float uu = in ? u[off + (size_t)i*Sc + t] : 0.f;
        sC[rr][t] = c;
        sU[rr][t] = uu;
        sL[rr][t] = logf(fmaxf(c, EPSF));
    }
    __syncthreads();

#pragma unroll
    for (int k = 0; k < 4; k++) {
        int i = r0 + k;
        int w = k + 1;
        int idx = i*Sc + t;
        float c = sC[w][t];

        // packed face coefficients
        float cfx = 0.f, cfy = 0.f;
        if (i < Sc-1) { float cn = sC[w+1][t]; cfx = (2.f*c*cn / (c + cn + EPSF)) * INVH2; }
        if (t < Sc-1) { float ce = sC[w][t+1]; cfy = (2.f*c*ce / (c + ce + EPSF)) * INVH2; }
        g_cf[off+idx] = make_float2(cfx, cfy);

        // laplacian (same fp expression as validated rounds)
        float lap = 0.f;
        bool interior = (i > 0 && i < Sc-1 && t > 0 && t < Sc-1);
        if (interior) {
            float uc = sU[w][t];
            lap = ((sU[w+1][t]-uc)*INVH - (uc-sU[w-1][t])*INVH)*INVH
                + ((sU[w][t+1]-uc)*INVH - (uc-sU[w][t-1])*INVH)*INVH;
        }
        g_lap[off+idx] = lap;

        // log-gradient from smem tiles
        float lc = sL[w][t];
        float glx, gly;
        if (i == 0)          glx = (sL[w+1][t] - lc) * INVH;
        else if (i == Sc-1)  glx = (lc - sL[w-1][t]) * INVH;
        else                 glx = (sL[w+1][t] - sL[w-1][t]) * (0.5f*INVH);
        if (t == 0)          gly = (sL[w][t+1] - lc) * INVH;
        else if (t == Sc-1)  gly = (lc - sL[w][t-1]) * INVH;
        else                 gly = (sL[w][t+1] - sL[w][t-1]) * (0.5f*INVH);

        float eta = sqrtf(glx*glx + gly*gly + EPSF);
        float rho = 1.f / (1.f + expf(-GAMMA_F * (eta - THRESH_F)));
        float nhx = glx / eta, nhy = gly / eta;

        float4 bv = B4[idx];
        g_rho[off+idx] = rho;
        g_P[off+idx]   = bv.y*nhx - bv.z*nhy;
        g_Q[off+idx]   = bv.y*nhy + bv.z*nhx;
        g_BB[off+idx]  = bv.x;

        // boundary geometry: integer argmin; double only on anti-diagonal ties
        float bnx, bny, dd;
        if (i + t != 511) {
            int m0 = i, m1 = 511-i, m2 = t, m3 = 511-t;
            int best = m0, kk = 0;
            if (m1 < best) { best = m1; kk = 1; }
            if (m2 < best) { best = m2; kk = 2; }
            if (m3 < best) { best = m3; kk = 3; }
            bnx = (kk == 0) ? -1.f : ((kk == 1) ? 1.f : 0.f);
            bny = (kk == 2) ? -1.f : ((kk == 3) ? 1.f : 0.f);
            dd = (float)((double)best * (1.0/511.0));
        } else {
            double dl = 1.0 / 511.0;
            double xx = (i == Sc-1) ? 1.0 : (double)i * dl;
            double yy = (t == Sc-1) ? 1.0 : (double)t * dl;
            double a0 = xx, a1 = 1.0 - xx, a2 = yy, a3 = 1.0 - yy;
            double best = a0; int kk = 0;
            if (a1 < best) { best = a1; kk = 1; }
            if (a2 < best) { best = a2; kk = 2; }
            if (a3 < best) { best = a3; kk = 3; }
            bnx = (kk == 0) ? -1.f : ((kk == 1) ? 1.f : 0.f);
            bny = (kk == 2) ? -1.f : ((kk == 3) ? 1.f : 0.f);
            dd = (float)best;
        }
        g_BNX[off+idx] = bv.w * bnx;
        g_BNY[off+idx] = bv.w * bny;
        if (b == 0) g_RB[idx] = expf(-(dd*dd) / (0.15f*0.15f));
    }
}

// =====================================================================
// S2: rhs -> g_r  (unchanged structure)
// =====================================================================
#define NBs 128
#define TPBs 256
#define CPBs (Nc/NBs)

__device__ __forceinline__ float fluxX(const float* C, const float* U, const float* LAP,
                                       const float* RHO, const float* PP, const float* BB,
                                       const float* BNX, int a) {
    int b2 = a + Sc;
    float ca = C[a], cb = C[b2];
    float cxf = 2.f*ca*cb / (ca + cb + EPSF);
    float gux = (U[b2] - U[a]) * INVH;
    float lgx = (LAP[b2] - LAP[a]) * INVH;
    return 0.5f*(BB[a]+BB[b2]) * HH * cxf * lgx
         + 0.5f*(RHO[a]+RHO[b2]) * (0.5f*(PP[a]+PP[b2])) * cxf * gux
         + 0.5f*(g_RB[a]+g_RB[b2]) * (0.5f*(BNX[a]+BNX[b2])) * cxf * gux;
}

__device__ __forceinline__ float fluxY(const float* C, const float* U, const float* LAP,
                                       const float* RHO, const float* QQ, const float* BB,
                                       const float* BNY, int a) {
    int b2 = a + 1;
    float ca = C[a], cb = C[b2];
    float cyf = 2.f*ca*cb / (ca + cb + EPSF);
    float guy = (U[b2] - U[a]) * INVH;
    float lgy = (LAP[b2] - LAP[a]) * INVH;
    return 0.5f*(BB[a]+BB[b2]) * HH * cyf * lgy
         + 0.5f*(RHO[a]+RHO[b2]) * (0.5f*(QQ[a]+QQ[b2])) * cyf * guy
         + 0.5f*(g_RB[a]+g_RB[b2]) * (0.5f*(BNY[a]+BNY[b2])) * cyf * guy;
}

__global__ void s2_kernel(const float* __restrict__ coeff, const float* __restrict__ u) {
    int b = blockIdx.y;
    size_t off = (size_t)b * Nc;
    const float* C = coeff + off;
    const float* U = u + off;
    const float* LAP = g_lap + off;
    const float* RHO = g_rho + off;
    const float* PP  = g_P + off;
    const float* QQ  = g_Q + off;
    const float* BB  = g_BB + off;
    const float* BNX = g_BNX + off;
    const float* BNY = g_BNY + off;
    int base = blockIdx.x * CPBs;

    for (int t = threadIdx.x; t < CPBs; t += TPBs) {
        int idx = base + t;
        int i = idx >> 9;
        int j = idx & (Sc - 1);
        float rhs = 0.f;
        if (i > 0 && i < Sc-1 && j > 0 && j < Sc-1) {
            float fxN = fluxX(C, U, LAP, RHO, PP, BB, BNX, idx);
            float fxS = fluxX(C, U, LAP, RHO, PP, BB, BNX, idx - Sc);
            float fyE = fluxY(C, U, LAP, RHO, QQ, BB, BNY, idx);
            float fyW = fluxY(C, U, LAP, RHO, QQ, BB, BNY, idx - 1);
            rhs = (fxN - fxS) * INVH + (fyE - fyW) * INVH;
        }
        g_r[off+idx] = rhs;
    }
}

__global__ void zc_kernel() {
    if (threadIdx.x < Bc) {
        g_cnt[threadIdx.x] = 0u;
        g_pubA[threadIdx.x] = 0ull;
        g_pubB[threadIdx.x] = 0ull;
    }
}

// =====================================================================
// one barrier: deterministic reduction of two dots + fence
// =====================================================================
__device__ __forceinline__ float2 sync_reduce2(float va, float vb, float* sRed,
                                               int b, int rblk, unsigned ev) {
#pragma unroll
    for (int o = 16; o > 0; o >>= 1) {
        va += __shfl_down_sync(0xffffffffu, va, o);
        vb += __shfl_down_sync(0xffffffffu, vb, o);
    }
    if ((threadIdx.x & 31) == 0) {
        sRed[2*(threadIdx.x >> 5)]   = va;
        sRed[2*(threadIdx.x >> 5)+1] = vb;
    }
    __syncthreads();
    if (threadIdx.x == 0) {
        float sa = 0.f, sb = 0.f;
#pragma unroll
        for (int w = 0; w < 16; w++) { sa += sRed[2*w]; sb += sRed[2*w+1]; }
        g_part[b*BPB + rblk] = make_float2(sa, sb);
        unsigned old;
        asm volatile("atom.acq_rel.gpu.global.add.u32 %0, [%1], %2;"
                     : "=r"(old) : "l"(&g_cnt[b]), "r"(1u) : "memory");
        if (old == ev*BPB - 1u) {
            const float2* pp = &g_part[b*BPB];
            float ga = 0.f, gb2 = 0.f;
#pragma unroll
            for (int i = 0; i < BPB; i++) { float2 v = pp[i]; ga += v.x; gb2 += v.y; }
            unsigned long long pkA = ((unsigned long long)ev << 32) |
                                     (unsigned long long)__float_as_uint(ga);
            unsigned long long pkB = ((unsigned long long)ev << 32) |
                                     (unsigned long long)__float_as_uint(gb2);
            asm volatile("st.release.gpu.global.b64 [%0], %1;" :: "l"(&g_pubA[b]), "l"(pkA) : "memory");
            asm volatile("st.release.gpu.global.b64 [%0], %1;" :: "l"(&g_pubB[b]), "l"(pkB) : "memory");
            sRed[0] = ga; sRed[1] = gb2;
        } else {
            unsigned long long pk;
            do {
                asm volatile("ld.acquire.gpu.global.b64 %0, [%1];"
                             : "=l"(pk) : "l"(&g_pubB[b]) : "memory");
            } while ((unsigned)(pk >> 32) != ev);
            sRed[1] = __uint_as_float((unsigned)pk);
            do {
                asm volatile("ld.acquire.gpu.global.b64 %0, [%1];"
                             : "=l"(pk) : "l"(&g_pubA[b]) : "memory");
            } while ((unsigned)(pk >> 32) != ev);
            sRed[0] = __uint_as_float((unsigned)pk);
        }
    }
    __syncthreads();
    float2 r = make_float2(sRed[0], sRed[1]);
    __syncthreads();
    return r;
}

#define SMEM_FLOATS (3*RMAX*PT + 64)
#define SMEM_BYTES (SMEM_FLOATS * 4)

// =====================================================================
// Persistent pipelined-CG, 296 perfectly-balanced blocks
// =====================================================================
__global__ void __launch_bounds__(PT, 2)
cg_kernel(const float* __restrict__ u, float* __restrict__ out) {
    extern __shared__ float sm[];
    float* sW   = sm;
    float* sS   = sm + RMAX*PT;
    float* sZ   = sS + RMAX*PT;
    float* sRed = sZ + RMAX*PT;

    const int t = threadIdx.x;
    const int blk = blockIdx.x;
    const int b = blk / BPB;
    const int rblk = blk - b*BPB;
    const int start = (rblk < 31) ? rblk*14 : 434 + (rblk-31)*13;
    const int nr = (rblk < 31) ? 14 : 13;
    const size_t off = (size_t)b * Nc;
    const size_t gb = off + (size_t)start * Sc + t;
    const float2* __restrict__ CF = g_cf + off;
    unsigned ev = 0;

    const bool interiorT = (t > 0 && t < Sc-1);
    const int tcy = (t > 0) ? t-1 : 0;
    float r[RMAX], p[RMAX], x[RMAX];

    // ---- init: load r, stage in sS, w0 = A r0, dots ----
#pragma unroll
    for (int k = 0; k < RMAX; k++) {
        bool act = (k < nr);
        float rv = act ? g_r[gb + k*Sc] : 0.f;
        r[k] = rv;
        sS[k*PT + t] = rv;
        p[k] = 0.f;
        x[k] = 0.f;
    }
    __syncthreads();

    float accA = 0.f, accB = 0.f;
    {
        float rHT = (rblk > 0)     ? g_r[gb - Sc]     : 0.f;
        float rHB = (rblk < BPB-1) ? g_r[gb + nr*Sc]  : 0.f;
        float cxp = CF[(size_t)(start > 0 ? start-1 : 0)*Sc + t].x;
#pragma unroll
        for (int k = 0; k < RMAX; k++) {
            bool act = (k < nr);
            int i = start + k;
            int ii = act ? i : Sc-1;
            float2 cf = CF[(size_t)ii*Sc + t];
            float cye = cf.y;
            float cyw = __shfl_up_sync(0xffffffffu, cye, 1);
            if ((t & 31) == 0) cyw = CF[(size_t)ii*Sc + tcy].y;
            float w = 0.f;
            if (act && i > 0 && i < Sc-1 && interiorT) {
                float rc = r[k];
                float ru = (k == nr-1) ? rHB : sS[(k+1)*PT + t];
                float rd = (k == 0)    ? rHT : sS[(k-1)*PT + t];
                float re = sS[k*PT + t + 1];
                float rw_ = sS[k*PT + t - 1];
                w = cf.x*(rc-ru) + cxp*(rc-rd) + cye*(rc-re) + cyw*(rc-rw_);
            }
            sW[k*PT + t] = w;
            accA += r[k]*r[k];
            accB += w*r[k];
            if (act && (k == 0 || k == nr-1)) g_w[gb + k*Sc] = w;
            cxp = cf.x;
        }
    }
    __syncthreads();
#pragma unroll
    for (int k = 0; k < RMAX; k++) { sS[k*PT + t] = 0.f; sZ[k*PT + t] = 0.f; }

    float gamma_old = 1.f, alpha_old = 1.f;

    for (int it = 0; it < ITERS; it++) {
        ev++;
        float2 gd = sync_reduce2(accA, accB, sRed, b, rblk, ev);
        float G = gd.x, D = gd.y;
        float beta, alpha;
        if (it == 0) {
            beta = 0.f;
            alpha = G / fmaxf(D, EPSF);
        } else {
            beta = G / fmaxf(gamma_old, EPSF);
            float den = D - beta * G / alpha_old;
            alpha = G / fmaxf(den, EPSF);
        }

        if (it == ITERS-1) {
#pragma unroll
            for (int k = 0; k < RMAX; k++) {
                float pv = r[k] + beta * p[k];
                x[k] += alpha * pv;
            }
            break;
        }

        // ---- pass 1: q = A w ; z = q + beta*z ----
        {
            float wHT = (rblk > 0)     ? g_w[gb - Sc]     : 0.f;
            float wHB = (rblk < BPB-1) ? g_w[gb + nr*Sc]  : 0.f;
            float cxp = CF[(size_t)(start > 0 ? start-1 : 0)*Sc + t].x;
#pragma unroll
            for (int k = 0; k < RMAX; k++) {
                bool act = (k < nr);
                int i = start + k;
                int ii = act ? i : Sc-1;
                float2 cf = CF[(size_t)ii*Sc + t];
                float cye = cf.y;
                float cyw = __shfl_up_sync(0xffffffffu, cye, 1);
                if ((t & 31) == 0) cyw = CF[(size_t)ii*Sc + tcy].y;
                float q = 0.f;
                if (act && i > 0 && i < Sc-1 && interiorT) {
                    float wc = sW[k*PT + t];
                    float wu = (k == nr-1) ? wHB : sW[(k+1)*PT + t];
                    float wd = (k == 0)    ? wHT : sW[(k-1)*PT + t];
                    float we = sW[k*PT + t + 1];
                    float ww = sW[k*PT + t - 1];
                    q = cf.x*(wc-wu) + cxp*(wc-wd) + cye*(wc-we) + cyw*(wc-ww);
                }
                sZ[k*PT + t] = q + beta * sZ[k*PT + t];
                cxp = cf.x;
            }
        }
        __syncthreads();

        // ---- pass 2: recurrences + next dots + edge-w exchange ----
        accA = 0.f; accB = 0.f;
#pragma unroll
        for (int k = 0; k < RMAX; k++) {
            bool act = (k < nr);
            float wc = sW[k*PT + t];
            float sv = wc + beta * sS[k*PT + t];
            sS[k*PT + t] = sv;
            float pv = r[k] + beta * p[k];
            p[k] = pv;
            x[k] += alpha * pv;
            float rv = r[k] - alpha * sv;
            r[k] = rv;
            float wv = wc - alpha * sZ[k*PT + t];
            sW[k*PT + t] = wv;
            accA += rv * rv;
            accB += wv * rv;
            if (act && (k == 0 || k == nr-1)) g_w[gb + k*Sc] = wv;
        }
        gamma_old = G;
        alpha_old = alpha;
    }

    // ---- output: out = zb(u + x) ----
#pragma unroll
    for (int k = 0; k < RMAX; k++) {
        bool act = (k < nr);
        if (!act) continue;
        int i = start + k;
        size_t gi = gb + k*Sc;
        float v = 0.f;
        if (i > 0 && i < Sc-1 && interiorT) v = u[gi] + x[k];
        out[gi] = v;
    }
}

extern "C" void kernel_launch(void* const* d_in, const int* in_sizes, int n_in,
                              void* d_out, int out_size) {
    const float* coeff = (const float*)d_in[0];
    const float* u     = (const float*)d_in[1];
    const float* beta  = (const float*)d_in[2];
    float* out = (float*)d_out;

    cudaFuncSetAttribute(cg_kernel, cudaFuncAttributeMaxDynamicSharedMemorySize, SMEM_BYTES);

    zc_kernel<<<1, 32>>>();
    dim3 g1(128, Bc);
    s1_kernel<<<g1, 512>>>(coeff, u, beta);
    dim3 g2(NBs, Bc);
    s2_kernel<<<g2, TPBs>>>(coeff, u);
    cg_kernel<<<PB, PT, SMEM_BYTES>>>(u, out);
}